// round 2
// baseline (speedup 1.0000x reference)
#include <cuda_runtime.h>
#include <cuda_bf16.h>
#include <math.h>

// Problem constants (from reference setup_inputs)
#define NMAX 50000
#define EMAX 800000
#define NEG_SLOPE 0.2f

// ---------------- static device scratch (no allocations allowed) -------------
__device__ float g_feat[NMAX * 128];   // current layer fc output [N,H*D]
__device__ float g_rstA[NMAX * 128];   // layer0 output (h1)
__device__ float g_rstB[NMAX * 128];   // layer1 output (h2)
__device__ float g_el[NMAX * 4];
__device__ float g_er[NMAX * 4];
__device__ float g_m[NMAX * 4];
__device__ float g_s[NMAX * 4];
__device__ float g_e[EMAX * 4];        // per-edge scores / exp values
__device__ float g_feat2[NMAX * 4];    // layer2 fc output

// ---------------- helpers ----------------------------------------------------
__device__ __forceinline__ void atomicMaxFloat(float* addr, float value) {
    // sign-split trick; correct for all finite floats and -inf init
    if (value >= 0.0f) {
        atomicMax((int*)addr, __float_as_int(value));
    } else {
        atomicMin((unsigned int*)addr, __float_as_uint(value));
    }
}

// zero rst[0..nrst) and set m=-inf, s=0 for [0..nms)
__global__ void init_layer_kernel(float* __restrict__ rst, int nrst,
                                  float* __restrict__ m, float* __restrict__ s,
                                  int nms) {
    int i = blockIdx.x * blockDim.x + threadIdx.x;
    if (i < nrst) rst[i] = 0.0f;
    if (i < nms) { m[i] = -INFINITY; s[i] = 0.0f; }
}

// ---------------- fused fc + attention projections (layers 0,1) --------------
// OUT=128 (4 heads x 32), one block of 128 threads per node.
__global__ void gemm_attn_kernel(const float* __restrict__ h,
                                 const float* __restrict__ W,
                                 const float* __restrict__ al,
                                 const float* __restrict__ ar,
                                 float* __restrict__ feat,
                                 float* __restrict__ el,
                                 float* __restrict__ er,
                                 int K, int N) {
    int node = blockIdx.x;
    if (node >= N) return;
    int t = threadIdx.x;  // 0..127

    __shared__ float hs[128];
    if (t < K) hs[t] = h[node * K + t];
    __syncthreads();

    float acc = 0.0f;
#pragma unroll 8
    for (int k = 0; k < K; k++) {
        acc += hs[k] * W[k * 128 + t];
    }
    feat[node * 128 + t] = acc;

    int head = t >> 5;
    int lane = t & 31;
    float va = acc * al[head * 32 + lane];
    float vb = acc * ar[head * 32 + lane];
#pragma unroll
    for (int o = 16; o > 0; o >>= 1) {
        va += __shfl_down_sync(0xFFFFFFFFu, va, o);
        vb += __shfl_down_sync(0xFFFFFFFFu, vb, o);
    }
    if (lane == 0) {
        el[node * 4 + head] = va;
        er[node * 4 + head] = vb;
    }
}

// ---------------- layer2 fc (K=128 -> OUT=4, H=1), one warp per node ---------
__global__ void gemm2_kernel(const float* __restrict__ h,
                             const float* __restrict__ W,
                             const float* __restrict__ al,
                             const float* __restrict__ ar,
                             float* __restrict__ feat2,
                             float* __restrict__ el,
                             float* __restrict__ er,
                             int N) {
    int warp = (blockIdx.x * blockDim.x + threadIdx.x) >> 5;
    int lane = threadIdx.x & 31;
    if (warp >= N) return;

    float a0 = 0.f, a1 = 0.f, a2 = 0.f, a3 = 0.f;
#pragma unroll
    for (int i = 0; i < 4; i++) {
        int k = lane + 32 * i;
        float hv = h[warp * 128 + k];
        const float4 w = *(const float4*)(W + k * 4);
        a0 += hv * w.x; a1 += hv * w.y; a2 += hv * w.z; a3 += hv * w.w;
    }
#pragma unroll
    for (int o = 16; o > 0; o >>= 1) {
        a0 += __shfl_down_sync(0xFFFFFFFFu, a0, o);
        a1 += __shfl_down_sync(0xFFFFFFFFu, a1, o);
        a2 += __shfl_down_sync(0xFFFFFFFFu, a2, o);
        a3 += __shfl_down_sync(0xFFFFFFFFu, a3, o);
    }
    if (lane == 0) {
        feat2[warp * 4 + 0] = a0;
        feat2[warp * 4 + 1] = a1;
        feat2[warp * 4 + 2] = a2;
        feat2[warp * 4 + 3] = a3;
        el[warp] = a0 * al[0] + a1 * al[1] + a2 * al[2] + a3 * al[3];
        er[warp] = a0 * ar[0] + a1 * ar[1] + a2 * ar[2] + a3 * ar[3];
    }
}

// ---------------- edge score + segment max ----------------------------------
__global__ void edge_max_kernel(const int* __restrict__ src,
                                const int* __restrict__ dst,
                                const float* __restrict__ el,
                                const float* __restrict__ er,
                                float* __restrict__ escr,
                                float* __restrict__ m,
                                int E, int H) {
    int total = E * H;
    for (int idx = blockIdx.x * blockDim.x + threadIdx.x; idx < total;
         idx += gridDim.x * blockDim.x) {
        int e = idx / H;
        int hh = idx - e * H;
        float v = el[src[e] * H + hh] + er[dst[e] * H + hh];
        v = (v > 0.0f) ? v : NEG_SLOPE * v;
        escr[idx] = v;
        atomicMaxFloat(&m[dst[e] * H + hh], v);
    }
}

// ---------------- exp + segment sum ------------------------------------------
__global__ void edge_expsum_kernel(const int* __restrict__ dst,
                                   float* __restrict__ escr,
                                   const float* __restrict__ m,
                                   float* __restrict__ s,
                                   int E, int H) {
    int total = E * H;
    for (int idx = blockIdx.x * blockDim.x + threadIdx.x; idx < total;
         idx += gridDim.x * blockDim.x) {
        int e = idx / H;
        int hh = idx - e * H;
        float ex = __expf(escr[idx] - m[dst[e] * H + hh]);
        escr[idx] = ex;
        atomicAdd(&s[dst[e] * H + hh], ex);
    }
}

// ---------------- message aggregation (H=4, D=32): one warp per edge ---------
__global__ void edge_aggr_kernel(const int* __restrict__ src,
                                 const int* __restrict__ dst,
                                 const float* __restrict__ feat,
                                 const float* __restrict__ escr,
                                 const float* __restrict__ s,
                                 float* __restrict__ rst,
                                 int E) {
    int w = (blockIdx.x * blockDim.x + threadIdx.x) >> 5;
    int lane = threadIdx.x & 31;
    if (w >= E) return;
    int si = src[w];
    int di = dst[w];
    int hh = lane >> 3;  // 8 lanes (= 32 floats) per head
    float alpha = escr[w * 4 + hh] / s[di * 4 + hh];
    const float4 f = *(const float4*)(feat + si * 128 + lane * 4);
    float4 v = make_float4(f.x * alpha, f.y * alpha, f.z * alpha, f.w * alpha);
    float* p = rst + di * 128 + lane * 4;
    asm volatile("red.global.add.v4.f32 [%0], {%1, %2, %3, %4};"
                 :: "l"(p), "f"(v.x), "f"(v.y), "f"(v.z), "f"(v.w)
                 : "memory");
}

// ---------------- layer2 aggregation (H=1, D=4): one thread per edge ---------
__global__ void edge_aggr2_kernel(const int* __restrict__ src,
                                  const int* __restrict__ dst,
                                  const float* __restrict__ feat2,
                                  const float* __restrict__ escr,
                                  const float* __restrict__ s,
                                  float* __restrict__ out,
                                  int E) {
    int e = blockIdx.x * blockDim.x + threadIdx.x;
    if (e >= E) return;
    int si = src[e];
    int di = dst[e];
    float alpha = escr[e] / s[di];
    const float4 f = *(const float4*)(feat2 + si * 4);
    float4 v = make_float4(f.x * alpha, f.y * alpha, f.z * alpha, f.w * alpha);
    float* p = out + di * 4;
    asm volatile("red.global.add.v4.f32 [%0], {%1, %2, %3, %4};"
                 :: "l"(p), "f"(v.x), "f"(v.y), "f"(v.z), "f"(v.w)
                 : "memory");
}

// ---------------- finalize: (+residual) + bias + ELU -------------------------
__global__ void finalize_kernel(float* __restrict__ rst,
                                const float* __restrict__ bias,
                                const float* __restrict__ resid,
                                int N, int applyAct) {
    int idx = blockIdx.x * blockDim.x + threadIdx.x;
    if (idx >= N * 128) return;
    int j = idx & 127;
    float v = rst[idx] + bias[j];
    if (resid) v += resid[idx];
    if (applyAct) v = (v > 0.0f) ? v : (__expf(v) - 1.0f);
    rst[idx] = v;
}

__global__ void finalize2_kernel(float* __restrict__ out,
                                 const float* __restrict__ bias,
                                 int N) {
    int idx = blockIdx.x * blockDim.x + threadIdx.x;
    if (idx >= N * 4) return;
    out[idx] += bias[idx & 3];
}

// ---------------- host launcher ----------------------------------------------
extern "C" void kernel_launch(void* const* d_in, const int* in_sizes, int n_in,
                              void* d_out, int out_size) {
    const float* x   = (const float*)d_in[0];
    const int*   src = (const int*)d_in[1];
    const int*   dst = (const int*)d_in[2];
    const float* W0  = (const float*)d_in[3];
    const float* al0 = (const float*)d_in[4];
    const float* ar0 = (const float*)d_in[5];
    const float* b0  = (const float*)d_in[6];
    const float* W1  = (const float*)d_in[7];
    const float* al1 = (const float*)d_in[8];
    const float* ar1 = (const float*)d_in[9];
    const float* b1  = (const float*)d_in[10];
    const float* W2  = (const float*)d_in[11];
    const float* al2 = (const float*)d_in[12];
    const float* ar2 = (const float*)d_in[13];
    const float* b2  = (const float*)d_in[14];

    int N = in_sizes[0] / 64;
    int E = in_sizes[1];

    float *feat, *rstA, *rstB, *el, *er, *m, *s, *escr, *feat2;
    cudaGetSymbolAddress((void**)&feat,  g_feat);
    cudaGetSymbolAddress((void**)&rstA,  g_rstA);
    cudaGetSymbolAddress((void**)&rstB,  g_rstB);
    cudaGetSymbolAddress((void**)&el,    g_el);
    cudaGetSymbolAddress((void**)&er,    g_er);
    cudaGetSymbolAddress((void**)&m,     g_m);
    cudaGetSymbolAddress((void**)&s,     g_s);
    cudaGetSymbolAddress((void**)&escr,  g_e);
    cudaGetSymbolAddress((void**)&feat2, g_feat2);

    float* out = (float*)d_out;

    const int TB = 256;
    int gridEH4 = (E * 4 + TB - 1) / TB;
    int gridE   = (E + TB - 1) / TB;
    int gridEW  = (E * 32 + TB - 1) / TB;      // warp per edge
    int gridN128 = (N * 128 + TB - 1) / TB;
    int gridN4   = (N * 4 + TB - 1) / TB;

    // ================= layer 0 (K=64) =================
    gemm_attn_kernel<<<N, 128>>>(x, W0, al0, ar0, feat, el, er, 64, N);
    init_layer_kernel<<<gridN128, TB>>>(rstA, N * 128, m, s, N * 4);
    edge_max_kernel<<<gridEH4, TB>>>(src, dst, el, er, escr, m, E, 4);
    edge_expsum_kernel<<<gridEH4, TB>>>(dst, escr, m, s, E, 4);
    edge_aggr_kernel<<<gridEW, TB>>>(src, dst, feat, escr, s, rstA, E);
    finalize_kernel<<<gridN128, TB>>>(rstA, b0, nullptr, N, 1);

    // ================= layer 1 (K=128, residual) =================
    gemm_attn_kernel<<<N, 128>>>(rstA, W1, al1, ar1, feat, el, er, 128, N);
    init_layer_kernel<<<gridN128, TB>>>(rstB, N * 128, m, s, N * 4);
    edge_max_kernel<<<gridEH4, TB>>>(src, dst, el, er, escr, m, E, 4);
    edge_expsum_kernel<<<gridEH4, TB>>>(dst, escr, m, s, E, 4);
    edge_aggr_kernel<<<gridEW, TB>>>(src, dst, feat, escr, s, rstB, E);
    finalize_kernel<<<gridN128, TB>>>(rstB, b1, rstA, N, 1);

    // ================= layer 2 (K=128 -> 4, H=1) =================
    gemm2_kernel<<<(N * 32 + TB - 1) / TB, TB>>>(rstB, W2, al2, ar2, feat2, el, er, N);
    init_layer_kernel<<<gridN4, TB>>>(out, N * 4, m, s, N);
    edge_max_kernel<<<gridE, TB>>>(src, dst, el, er, escr, m, E, 1);
    edge_expsum_kernel<<<gridE, TB>>>(dst, escr, m, s, E, 1);
    edge_aggr2_kernel<<<gridE, TB>>>(src, dst, feat2, escr, s, out, E);
    finalize2_kernel<<<gridN4, TB>>>(out, b2, N);
}

// round 3
// speedup vs baseline: 1.0674x; 1.0674x over previous
#include <cuda_runtime.h>
#include <cuda_bf16.h>
#include <math.h>

#define NMAX 50000
#define EMAX 800000
#define NEG_SLOPE 0.2f

// ---------------- static device scratch --------------------------------------
__device__ float g_feat[NMAX * 128];   // current layer fc output [N,H*D]
__device__ float g_rstA[NMAX * 128];   // layer0 output (h1)
__device__ float g_rstB[NMAX * 128];   // layer1 output (h2)
__device__ float g_el[NMAX * 4];
__device__ float g_er[NMAX * 4];
__device__ float g_s[NMAX * 4];        // per-(node,head) exp-sum
__device__ float g_feat2[NMAX * 4];    // layer2 fc output

// ---------------- init: zero rst and s ---------------------------------------
__global__ void init_layer_kernel(float* __restrict__ rst, int nrst,
                                  float* __restrict__ s, int ns) {
    int i = blockIdx.x * blockDim.x + threadIdx.x;
    if (i < nrst) rst[i] = 0.0f;
    if (i < ns) s[i] = 0.0f;
}

// ---------------- fused fc + attention projections (layers 0,1) --------------
// OUT=128 (4 heads x 32), one block of 128 threads per node.
__global__ void gemm_attn_kernel(const float* __restrict__ h,
                                 const float* __restrict__ W,
                                 const float* __restrict__ al,
                                 const float* __restrict__ ar,
                                 float* __restrict__ feat,
                                 float* __restrict__ el,
                                 float* __restrict__ er,
                                 int K, int N) {
    int node = blockIdx.x;
    if (node >= N) return;
    int t = threadIdx.x;  // 0..127

    __shared__ float hs[128];
    if (t < K) hs[t] = h[node * K + t];
    __syncthreads();

    float acc = 0.0f;
#pragma unroll 8
    for (int k = 0; k < K; k++) {
        acc += hs[k] * W[k * 128 + t];
    }
    feat[node * 128 + t] = acc;

    int head = t >> 5;
    int lane = t & 31;
    float va = acc * al[head * 32 + lane];
    float vb = acc * ar[head * 32 + lane];
#pragma unroll
    for (int o = 16; o > 0; o >>= 1) {
        va += __shfl_down_sync(0xFFFFFFFFu, va, o);
        vb += __shfl_down_sync(0xFFFFFFFFu, vb, o);
    }
    if (lane == 0) {
        el[node * 4 + head] = va;
        er[node * 4 + head] = vb;
    }
}

// ---------------- layer2 fc (K=128 -> OUT=4, H=1), one warp per node ---------
__global__ void gemm2_kernel(const float* __restrict__ h,
                             const float* __restrict__ W,
                             const float* __restrict__ al,
                             const float* __restrict__ ar,
                             float* __restrict__ feat2,
                             float* __restrict__ el,
                             float* __restrict__ er,
                             int N) {
    int warp = (blockIdx.x * blockDim.x + threadIdx.x) >> 5;
    int lane = threadIdx.x & 31;
    if (warp >= N) return;

    float a0 = 0.f, a1 = 0.f, a2 = 0.f, a3 = 0.f;
#pragma unroll
    for (int i = 0; i < 4; i++) {
        int k = lane + 32 * i;
        float hv = h[warp * 128 + k];
        const float4 w = *(const float4*)(W + k * 4);
        a0 += hv * w.x; a1 += hv * w.y; a2 += hv * w.z; a3 += hv * w.w;
    }
#pragma unroll
    for (int o = 16; o > 0; o >>= 1) {
        a0 += __shfl_down_sync(0xFFFFFFFFu, a0, o);
        a1 += __shfl_down_sync(0xFFFFFFFFu, a1, o);
        a2 += __shfl_down_sync(0xFFFFFFFFu, a2, o);
        a3 += __shfl_down_sync(0xFFFFFFFFu, a3, o);
    }
    if (lane == 0) {
        feat2[warp * 4 + 0] = a0;
        feat2[warp * 4 + 1] = a1;
        feat2[warp * 4 + 2] = a2;
        feat2[warp * 4 + 3] = a3;
        el[warp] = a0 * al[0] + a1 * al[1] + a2 * al[2] + a3 * al[3];
        er[warp] = a0 * ar[0] + a1 * ar[1] + a2 * ar[2] + a3 * ar[3];
    }
}

// ---------------- fused edge pass (layers 0,1): one warp per edge ------------
// ex = exp(leaky_relu(el[src]+er[dst])); s[dst] += ex; rst[dst] += ex*feat[src]
__global__ void edge_fused_kernel(const int* __restrict__ src,
                                  const int* __restrict__ dst,
                                  const float* __restrict__ el,
                                  const float* __restrict__ er,
                                  const float* __restrict__ feat,
                                  float* __restrict__ s,
                                  float* __restrict__ rst,
                                  int E) {
    int w = (blockIdx.x * blockDim.x + threadIdx.x) >> 5;
    int lane = threadIdx.x & 31;
    if (w >= E) return;
    int si = src[w];
    int di = dst[w];

    float ex4 = 0.0f;
    if (lane < 4) {
        float v = el[si * 4 + lane] + er[di * 4 + lane];
        v = (v > 0.0f) ? v : NEG_SLOPE * v;
        ex4 = __expf(v);
        asm volatile("red.global.add.f32 [%0], %1;"
                     :: "l"(s + di * 4 + lane), "f"(ex4) : "memory");
    }
    int hh = lane >> 3;  // head for this group of 8 lanes (32 floats)
    float ex = __shfl_sync(0xFFFFFFFFu, ex4, hh);

    const float4 f = *(const float4*)(feat + si * 128 + lane * 4);
    float4 v = make_float4(f.x * ex, f.y * ex, f.z * ex, f.w * ex);
    float* p = rst + di * 128 + lane * 4;
    asm volatile("red.global.add.v4.f32 [%0], {%1, %2, %3, %4};"
                 :: "l"(p), "f"(v.x), "f"(v.y), "f"(v.z), "f"(v.w)
                 : "memory");
}

// ---------------- fused edge pass (layer 2, H=1, D=4): thread per edge -------
__global__ void edge_fused2_kernel(const int* __restrict__ src,
                                   const int* __restrict__ dst,
                                   const float* __restrict__ el,
                                   const float* __restrict__ er,
                                   const float* __restrict__ feat2,
                                   float* __restrict__ s,
                                   float* __restrict__ out,
                                   int E) {
    int e = blockIdx.x * blockDim.x + threadIdx.x;
    if (e >= E) return;
    int si = src[e];
    int di = dst[e];
    float v = el[si] + er[di];
    v = (v > 0.0f) ? v : NEG_SLOPE * v;
    float ex = __expf(v);
    asm volatile("red.global.add.f32 [%0], %1;"
                 :: "l"(s + di), "f"(ex) : "memory");
    const float4 f = *(const float4*)(feat2 + si * 4);
    float4 m = make_float4(f.x * ex, f.y * ex, f.z * ex, f.w * ex);
    float* p = out + di * 4;
    asm volatile("red.global.add.v4.f32 [%0], {%1, %2, %3, %4};"
                 :: "l"(p), "f"(m.x), "f"(m.y), "f"(m.z), "f"(m.w)
                 : "memory");
}

// ---------------- finalize: normalize + (residual) + bias + ELU --------------
__global__ void finalize_kernel(float* __restrict__ rst,
                                const float* __restrict__ s,
                                const float* __restrict__ bias,
                                const float* __restrict__ resid,
                                int N, int applyAct) {
    int idx = blockIdx.x * blockDim.x + threadIdx.x;
    if (idx >= N * 128) return;
    int j = idx & 127;
    int node = idx >> 7;
    int head = j >> 5;
    float sv = s[node * 4 + head];
    float v = (sv > 0.0f) ? rst[idx] / sv : 0.0f;
    v += bias[j];
    if (resid) v += resid[idx];
    if (applyAct) v = (v > 0.0f) ? v : (__expf(v) - 1.0f);
    rst[idx] = v;
}

__global__ void finalize2_kernel(float* __restrict__ out,
                                 const float* __restrict__ s,
                                 const float* __restrict__ bias,
                                 int N) {
    int idx = blockIdx.x * blockDim.x + threadIdx.x;
    if (idx >= N * 4) return;
    float sv = s[idx >> 2];
    float v = (sv > 0.0f) ? out[idx] / sv : 0.0f;
    out[idx] = v + bias[idx & 3];
}

// ---------------- host launcher ----------------------------------------------
extern "C" void kernel_launch(void* const* d_in, const int* in_sizes, int n_in,
                              void* d_out, int out_size) {
    const float* x   = (const float*)d_in[0];
    const int*   src = (const int*)d_in[1];
    const int*   dst = (const int*)d_in[2];
    const float* W0  = (const float*)d_in[3];
    const float* al0 = (const float*)d_in[4];
    const float* ar0 = (const float*)d_in[5];
    const float* b0  = (const float*)d_in[6];
    const float* W1  = (const float*)d_in[7];
    const float* al1 = (const float*)d_in[8];
    const float* ar1 = (const float*)d_in[9];
    const float* b1  = (const float*)d_in[10];
    const float* W2  = (const float*)d_in[11];
    const float* al2 = (const float*)d_in[12];
    const float* ar2 = (const float*)d_in[13];
    const float* b2  = (const float*)d_in[14];

    int N = in_sizes[0] / 64;
    int E = in_sizes[1];

    float *feat, *rstA, *rstB, *el, *er, *s, *feat2;
    cudaGetSymbolAddress((void**)&feat,  g_feat);
    cudaGetSymbolAddress((void**)&rstA,  g_rstA);
    cudaGetSymbolAddress((void**)&rstB,  g_rstB);
    cudaGetSymbolAddress((void**)&el,    g_el);
    cudaGetSymbolAddress((void**)&er,    g_er);
    cudaGetSymbolAddress((void**)&s,     g_s);
    cudaGetSymbolAddress((void**)&feat2, g_feat2);

    float* out = (float*)d_out;

    const int TB = 256;
    int gridE    = (E + TB - 1) / TB;
    int gridEW   = (E * 32 + TB - 1) / TB;   // warp per edge
    int gridN128 = (N * 128 + TB - 1) / TB;
    int gridN4   = (N * 4 + TB - 1) / TB;

    // ================= layer 0 (K=64) =================
    gemm_attn_kernel<<<N, 128>>>(x, W0, al0, ar0, feat, el, er, 64, N);
    init_layer_kernel<<<gridN128, TB>>>(rstA, N * 128, s, N * 4);
    edge_fused_kernel<<<gridEW, TB>>>(src, dst, el, er, feat, s, rstA, E);
    finalize_kernel<<<gridN128, TB>>>(rstA, s, b0, nullptr, N, 1);

    // ================= layer 1 (K=128, residual) =================
    gemm_attn_kernel<<<N, 128>>>(rstA, W1, al1, ar1, feat, el, er, 128, N);
    init_layer_kernel<<<gridN128, TB>>>(rstB, N * 128, s, N * 4);
    edge_fused_kernel<<<gridEW, TB>>>(src, dst, el, er, feat, s, rstB, E);
    finalize_kernel<<<gridN128, TB>>>(rstB, s, b1, rstA, N, 1);

    // ================= layer 2 (K=128 -> 4, H=1) =================
    gemm2_kernel<<<(N * 32 + TB - 1) / TB, TB>>>(rstB, W2, al2, ar2, feat2, el, er, N);
    init_layer_kernel<<<gridN4, TB>>>(out, N * 4, s, N);
    edge_fused2_kernel<<<gridE, TB>>>(src, dst, el, er, feat2, s, out, E);
    finalize2_kernel<<<gridN4, TB>>>(out, s, b2, N);
}

// round 4
// speedup vs baseline: 1.2395x; 1.1612x over previous
#include <cuda_runtime.h>
#include <cuda_bf16.h>
#include <math.h>

#define NMAX 50000
#define EMAX 800000
#define NEG_SLOPE 0.2f

// ---------------- static device scratch --------------------------------------
__device__ float g_feat[NMAX * 128];   // current layer fc output [N,H*D]
__device__ float g_rstA[NMAX * 128];   // layer0 output (h1)
__device__ float g_rstB[NMAX * 128];   // layer1 output (h2)
__device__ float g_el[NMAX * 4];
__device__ float g_er[NMAX * 4];
__device__ float g_feat2[NMAX * 4];    // layer2 fc output
__device__ int   g_count[NMAX];
__device__ int   g_rowptr[NMAX + 1];
__device__ int   g_cursor[NMAX];
__device__ int   g_csrsrc[EMAX];

// ---------------- CSR build ---------------------------------------------------
__global__ void count_kernel(const int* __restrict__ dst, int* __restrict__ count,
                             int E) {
    int e = blockIdx.x * blockDim.x + threadIdx.x;
    if (e < E) atomicAdd(&count[dst[e]], 1);
}

// single-block exclusive scan over count[0..n) -> rowptr/cursor; rowptr[n]=total
__global__ void scan_kernel(const int* __restrict__ count,
                            int* __restrict__ rowptr,
                            int* __restrict__ cursor, int n) {
    __shared__ int ssum[1024];
    int t = threadIdx.x;
    int chunk = (n + 1023) >> 10;
    int begin = t * chunk;
    int end = min(begin + chunk, n);
    int sum = 0;
    for (int i = begin; i < end; i++) sum += count[i];
    ssum[t] = sum;
    __syncthreads();
    // Hillis-Steele inclusive scan
    for (int off = 1; off < 1024; off <<= 1) {
        int v = (t >= off) ? ssum[t - off] : 0;
        __syncthreads();
        ssum[t] += v;
        __syncthreads();
    }
    int prefix = (t == 0) ? 0 : ssum[t - 1];
    for (int i = begin; i < end; i++) {
        rowptr[i] = prefix;
        cursor[i] = prefix;
        prefix += count[i];
    }
    if (t == 0) rowptr[n] = ssum[1023];
}

__global__ void fill_csr_kernel(const int* __restrict__ src,
                                const int* __restrict__ dst,
                                int* __restrict__ cursor,
                                int* __restrict__ csrsrc, int E) {
    int e = blockIdx.x * blockDim.x + threadIdx.x;
    if (e < E) {
        int pos = atomicAdd(&cursor[dst[e]], 1);
        csrsrc[pos] = src[e];
    }
}

// ---------------- fused fc + attention projections (layers 0,1) --------------
// OUT=128 (4 heads x 32), one block of 128 threads per node.
__global__ void gemm_attn_kernel(const float* __restrict__ h,
                                 const float* __restrict__ W,
                                 const float* __restrict__ al,
                                 const float* __restrict__ ar,
                                 float* __restrict__ feat,
                                 float* __restrict__ el,
                                 float* __restrict__ er,
                                 int K, int N) {
    int node = blockIdx.x;
    if (node >= N) return;
    int t = threadIdx.x;  // 0..127

    __shared__ float hs[128];
    if (t < K) hs[t] = h[node * K + t];
    __syncthreads();

    float acc = 0.0f;
#pragma unroll 8
    for (int k = 0; k < K; k++) {
        acc += hs[k] * W[k * 128 + t];
    }
    feat[node * 128 + t] = acc;

    int head = t >> 5;
    int lane = t & 31;
    float va = acc * al[head * 32 + lane];
    float vb = acc * ar[head * 32 + lane];
#pragma unroll
    for (int o = 16; o > 0; o >>= 1) {
        va += __shfl_down_sync(0xFFFFFFFFu, va, o);
        vb += __shfl_down_sync(0xFFFFFFFFu, vb, o);
    }
    if (lane == 0) {
        el[node * 4 + head] = va;
        er[node * 4 + head] = vb;
    }
}

// ---------------- layer2 fc (K=128 -> OUT=4, H=1), one warp per node ---------
__global__ void gemm2_kernel(const float* __restrict__ h,
                             const float* __restrict__ W,
                             const float* __restrict__ al,
                             const float* __restrict__ ar,
                             float* __restrict__ feat2,
                             float* __restrict__ el,
                             float* __restrict__ er,
                             int N) {
    int warp = (blockIdx.x * blockDim.x + threadIdx.x) >> 5;
    int lane = threadIdx.x & 31;
    if (warp >= N) return;

    float a0 = 0.f, a1 = 0.f, a2 = 0.f, a3 = 0.f;
#pragma unroll
    for (int i = 0; i < 4; i++) {
        int k = lane + 32 * i;
        float hv = h[warp * 128 + k];
        const float4 w = *(const float4*)(W + k * 4);
        a0 += hv * w.x; a1 += hv * w.y; a2 += hv * w.z; a3 += hv * w.w;
    }
#pragma unroll
    for (int o = 16; o > 0; o >>= 1) {
        a0 += __shfl_down_sync(0xFFFFFFFFu, a0, o);
        a1 += __shfl_down_sync(0xFFFFFFFFu, a1, o);
        a2 += __shfl_down_sync(0xFFFFFFFFu, a2, o);
        a3 += __shfl_down_sync(0xFFFFFFFFu, a3, o);
    }
    if (lane == 0) {
        feat2[warp * 4 + 0] = a0;
        feat2[warp * 4 + 1] = a1;
        feat2[warp * 4 + 2] = a2;
        feat2[warp * 4 + 3] = a3;
        el[warp] = a0 * al[0] + a1 * al[1] + a2 * al[2] + a3 * al[3];
        er[warp] = a0 * ar[0] + a1 * ar[1] + a2 * ar[2] + a3 * ar[3];
    }
}

// ---------------- fused aggregation (layers 0,1) ------------------------------
// Block of 128 threads per dst node. Register accumulation over in-edges,
// softmax normalization deferred (divide by exp-sum at the end), then
// bias + optional residual + optional ELU, single store. No atomics.
__global__ void aggr_kernel(const int* __restrict__ rowptr,
                            const int* __restrict__ csrsrc,
                            const float* __restrict__ el,
                            const float* __restrict__ er,
                            const float* __restrict__ feat,
                            const float* __restrict__ bias,
                            const float* __restrict__ resid,
                            float* __restrict__ rst,
                            int N, int applyAct) {
    int di = blockIdx.x;
    if (di >= N) return;
    int t = threadIdx.x;      // 0..127
    int head = t >> 5;

    __shared__ int s_si[128];
    __shared__ float s_ex[128 * 4];

    int row0 = rowptr[di];
    int deg = rowptr[di + 1] - row0;

    const float4 er4 = *(const float4*)(er + di * 4);   // broadcast

    float acc = 0.0f;
    float sexp = 0.0f;

    for (int base = 0; base < deg; base += 128) {
        int e = base + t;
        if (e < deg) {
            int si = csrsrc[row0 + e];
            s_si[t] = si;
            const float4 elv = *(const float4*)(el + si * 4);
            float v0 = elv.x + er4.x; v0 = (v0 > 0.f) ? v0 : NEG_SLOPE * v0;
            float v1 = elv.y + er4.y; v1 = (v1 > 0.f) ? v1 : NEG_SLOPE * v1;
            float v2 = elv.z + er4.z; v2 = (v2 > 0.f) ? v2 : NEG_SLOPE * v2;
            float v3 = elv.w + er4.w; v3 = (v3 > 0.f) ? v3 : NEG_SLOPE * v3;
            s_ex[t * 4 + 0] = __expf(v0);
            s_ex[t * 4 + 1] = __expf(v1);
            s_ex[t * 4 + 2] = __expf(v2);
            s_ex[t * 4 + 3] = __expf(v3);
        }
        __syncthreads();
        int cnt = min(128, deg - base);
#pragma unroll 4
        for (int j = 0; j < cnt; j++) {
            float ex = s_ex[j * 4 + head];              // broadcast within warp
            acc += ex * feat[s_si[j] * 128 + t];        // coalesced 512B
            sexp += ex;
        }
        __syncthreads();
    }

    float v = (sexp > 0.0f) ? acc / sexp : 0.0f;
    v += bias[t];
    int idx = di * 128 + t;
    if (resid) v += resid[idx];
    if (applyAct) v = (v > 0.0f) ? v : (__expf(v) - 1.0f);
    rst[idx] = v;
}

// ---------------- fused aggregation (layer 2, H=1, D=4) ----------------------
// One warp per node; lanes split edges, butterfly reduce.
__global__ void aggr2_kernel(const int* __restrict__ rowptr,
                             const int* __restrict__ csrsrc,
                             const float* __restrict__ el,
                             const float* __restrict__ er,
                             const float* __restrict__ feat2,
                             const float* __restrict__ bias,
                             float* __restrict__ out,
                             int N) {
    int di = (blockIdx.x * blockDim.x + threadIdx.x) >> 5;
    int lane = threadIdx.x & 31;
    if (di >= N) return;

    int row0 = rowptr[di];
    int deg = rowptr[di + 1] - row0;
    float erd = er[di];

    float a0 = 0.f, a1 = 0.f, a2 = 0.f, a3 = 0.f, sexp = 0.f;
    for (int e = lane; e < deg; e += 32) {
        int si = csrsrc[row0 + e];
        float v = el[si] + erd;
        v = (v > 0.f) ? v : NEG_SLOPE * v;
        float ex = __expf(v);
        const float4 f = *(const float4*)(feat2 + si * 4);
        a0 += ex * f.x; a1 += ex * f.y; a2 += ex * f.z; a3 += ex * f.w;
        sexp += ex;
    }
#pragma unroll
    for (int o = 16; o > 0; o >>= 1) {
        a0 += __shfl_xor_sync(0xFFFFFFFFu, a0, o);
        a1 += __shfl_xor_sync(0xFFFFFFFFu, a1, o);
        a2 += __shfl_xor_sync(0xFFFFFFFFu, a2, o);
        a3 += __shfl_xor_sync(0xFFFFFFFFu, a3, o);
        sexp += __shfl_xor_sync(0xFFFFFFFFu, sexp, o);
    }
    if (lane == 0) {
        float inv = (sexp > 0.0f) ? 1.0f / sexp : 0.0f;
        out[di * 4 + 0] = a0 * inv + bias[0];
        out[di * 4 + 1] = a1 * inv + bias[1];
        out[di * 4 + 2] = a2 * inv + bias[2];
        out[di * 4 + 3] = a3 * inv + bias[3];
    }
}

// ---------------- host launcher ----------------------------------------------
extern "C" void kernel_launch(void* const* d_in, const int* in_sizes, int n_in,
                              void* d_out, int out_size) {
    const float* x   = (const float*)d_in[0];
    const int*   src = (const int*)d_in[1];
    const int*   dst = (const int*)d_in[2];
    const float* W0  = (const float*)d_in[3];
    const float* al0 = (const float*)d_in[4];
    const float* ar0 = (const float*)d_in[5];
    const float* b0  = (const float*)d_in[6];
    const float* W1  = (const float*)d_in[7];
    const float* al1 = (const float*)d_in[8];
    const float* ar1 = (const float*)d_in[9];
    const float* b1  = (const float*)d_in[10];
    const float* W2  = (const float*)d_in[11];
    const float* al2 = (const float*)d_in[12];
    const float* ar2 = (const float*)d_in[13];
    const float* b2  = (const float*)d_in[14];

    int N = in_sizes[0] / 64;
    int E = in_sizes[1];

    float *feat, *rstA, *rstB, *el, *er, *feat2;
    int *count, *rowptr, *cursor, *csrsrc;
    cudaGetSymbolAddress((void**)&feat,   g_feat);
    cudaGetSymbolAddress((void**)&rstA,   g_rstA);
    cudaGetSymbolAddress((void**)&rstB,   g_rstB);
    cudaGetSymbolAddress((void**)&el,     g_el);
    cudaGetSymbolAddress((void**)&er,     g_er);
    cudaGetSymbolAddress((void**)&feat2,  g_feat2);
    cudaGetSymbolAddress((void**)&count,  g_count);
    cudaGetSymbolAddress((void**)&rowptr, g_rowptr);
    cudaGetSymbolAddress((void**)&cursor, g_cursor);
    cudaGetSymbolAddress((void**)&csrsrc, g_csrsrc);

    float* out = (float*)d_out;

    const int TB = 256;
    int gridE = (E + TB - 1) / TB;

    // ---------- CSR build (reused by all 3 layers) ----------
    cudaMemsetAsync(count, 0, N * sizeof(int));
    count_kernel<<<gridE, TB>>>(dst, count, E);
    scan_kernel<<<1, 1024>>>(count, rowptr, cursor, N);
    fill_csr_kernel<<<gridE, TB>>>(src, dst, cursor, csrsrc, E);

    // ---------- layer 0 (K=64) ----------
    gemm_attn_kernel<<<N, 128>>>(x, W0, al0, ar0, feat, el, er, 64, N);
    aggr_kernel<<<N, 128>>>(rowptr, csrsrc, el, er, feat, b0, nullptr, rstA, N, 1);

    // ---------- layer 1 (K=128, residual) ----------
    gemm_attn_kernel<<<N, 128>>>(rstA, W1, al1, ar1, feat, el, er, 128, N);
    aggr_kernel<<<N, 128>>>(rowptr, csrsrc, el, er, feat, b1, rstA, rstB, N, 1);

    // ---------- layer 2 (K=128 -> 4, H=1) ----------
    gemm2_kernel<<<(N * 32 + TB - 1) / TB, TB>>>(rstB, W2, al2, ar2, feat2, el, er, N);
    aggr2_kernel<<<(N * 32 + TB - 1) / TB, TB>>>(rowptr, csrsrc, el, er, feat2, b2, out, N);
}

// round 5
// speedup vs baseline: 1.8243x; 1.4718x over previous
#include <cuda_runtime.h>
#include <cuda_bf16.h>
#include <math.h>

#define NMAX 50000
#define EMAX 800000
#define NEG_SLOPE 0.2f

// ---------------- static device scratch --------------------------------------
__device__ float g_feat[NMAX * 128];   // current layer fc output [N,H*D]
__device__ float g_rstA[NMAX * 128];   // layer0 output (h1)
__device__ float g_rstB[NMAX * 128];   // layer1 output (h2)
__device__ float g_el[NMAX * 4];
__device__ float g_er[NMAX * 4];
__device__ float g_feat2[NMAX * 4];    // layer2 fc output
__device__ int   g_count[NMAX];
__device__ int   g_rowptr[NMAX + 1];
__device__ int   g_cursor[NMAX];
__device__ int   g_csrsrc[EMAX];

// ---------------- f32x2 packed helpers (Blackwell) ---------------------------
__device__ __forceinline__ unsigned long long pack2(float x) {
    unsigned long long r;
    asm("mov.b64 %0, {%1, %1};" : "=l"(r) : "f"(x));
    return r;
}
__device__ __forceinline__ unsigned long long packpair(float lo, float hi) {
    unsigned long long r;
    asm("mov.b64 %0, {%1, %2};" : "=l"(r) : "f"(lo), "f"(hi));
    return r;
}
__device__ __forceinline__ unsigned long long fma2(unsigned long long a,
                                                   unsigned long long b,
                                                   unsigned long long c) {
    unsigned long long d;
    asm("fma.rn.f32x2 %0, %1, %2, %3;" : "=l"(d) : "l"(a), "l"(b), "l"(c));
    return d;
}
__device__ __forceinline__ void unpack2(unsigned long long p, float& lo, float& hi) {
    asm("mov.b64 {%0, %1}, %2;" : "=f"(lo), "=f"(hi) : "l"(p));
}

// ---------------- CSR build ---------------------------------------------------
__global__ void count_kernel(const int* __restrict__ dst, int* __restrict__ count,
                             int E) {
    int e = blockIdx.x * blockDim.x + threadIdx.x;
    if (e < E) atomicAdd(&count[dst[e]], 1);
}

__global__ void scan_kernel(const int* __restrict__ count,
                            int* __restrict__ rowptr,
                            int* __restrict__ cursor, int n) {
    __shared__ int ssum[1024];
    int t = threadIdx.x;
    int chunk = (n + 1023) >> 10;
    int begin = t * chunk;
    int end = min(begin + chunk, n);
    int sum = 0;
    for (int i = begin; i < end; i++) sum += count[i];
    ssum[t] = sum;
    __syncthreads();
    for (int off = 1; off < 1024; off <<= 1) {
        int v = (t >= off) ? ssum[t - off] : 0;
        __syncthreads();
        ssum[t] += v;
        __syncthreads();
    }
    int prefix = (t == 0) ? 0 : ssum[t - 1];
    for (int i = begin; i < end; i++) {
        rowptr[i] = prefix;
        cursor[i] = prefix;
        prefix += count[i];
    }
    if (t == 0) rowptr[n] = ssum[1023];
}

__global__ void fill_csr_kernel(const int* __restrict__ src,
                                const int* __restrict__ dst,
                                int* __restrict__ cursor,
                                int* __restrict__ csrsrc, int E) {
    int e = blockIdx.x * blockDim.x + threadIdx.x;
    if (e < E) {
        int pos = atomicAdd(&cursor[dst[e]], 1);
        csrsrc[pos] = src[e];
    }
}

// ---------------- register-tiled fc + attention projections ------------------
// Block = 256 threads, tile = 32 nodes x 128 cols. Thread (c = t&31, r = t>>5)
// computes 4 nodes (r*4..r*4+3) x 4 cols (c*4..c*4+3) with f32x2 FMAs.
#define HST_STRIDE 36
__global__ void gemm_attn2_kernel(const float* __restrict__ h,
                                  const float* __restrict__ W,
                                  const float* __restrict__ al,
                                  const float* __restrict__ ar,
                                  float* __restrict__ feat,
                                  float* __restrict__ el,
                                  float* __restrict__ er,
                                  int K, int N) {
    __shared__ float hsT[128 * HST_STRIDE];   // [k][node], padded
    int t = threadIdx.x;
    int node0 = blockIdx.x * 32;

    // cooperative transpose-load of h tile: 32 nodes x K floats
    for (int idx = t; idx < 32 * K; idx += 256) {
        int node = idx / K;
        int k = idx - node * K;
        float v = (node0 + node < N) ? h[(node0 + node) * K + k] : 0.0f;
        hsT[k * HST_STRIDE + node] = v;
    }
    __syncthreads();

    int c = t & 31;
    int r = t >> 5;
    int col0 = c * 4;

    unsigned long long acc00 = 0, acc01 = 0, acc10 = 0, acc11 = 0;
    unsigned long long acc20 = 0, acc21 = 0, acc30 = 0, acc31 = 0;

    for (int k = 0; k < K; k++) {
        const float4 w = *(const float4*)(W + k * 128 + col0);
        unsigned long long w01 = packpair(w.x, w.y);
        unsigned long long w23 = packpair(w.z, w.w);
        const float4 hv = *(const float4*)(&hsT[k * HST_STRIDE + r * 4]);
        unsigned long long h0 = pack2(hv.x);
        unsigned long long h1 = pack2(hv.y);
        unsigned long long h2 = pack2(hv.z);
        unsigned long long h3 = pack2(hv.w);
        acc00 = fma2(h0, w01, acc00);  acc01 = fma2(h0, w23, acc01);
        acc10 = fma2(h1, w01, acc10);  acc11 = fma2(h1, w23, acc11);
        acc20 = fma2(h2, w01, acc20);  acc21 = fma2(h2, w23, acc21);
        acc30 = fma2(h3, w01, acc30);  acc31 = fma2(h3, w23, acc31);
    }

    int head = c >> 3;
    const float4 al4 = *(const float4*)(al + col0);
    const float4 ar4 = *(const float4*)(ar + col0);

    unsigned long long accs[4][2] = {{acc00, acc01}, {acc10, acc11},
                                     {acc20, acc21}, {acc30, acc31}};
#pragma unroll
    for (int n = 0; n < 4; n++) {
        int node = node0 + r * 4 + n;
        float f0, f1, f2, f3;
        unpack2(accs[n][0], f0, f1);
        unpack2(accs[n][1], f2, f3);
        float pa = f0 * al4.x + f1 * al4.y + f2 * al4.z + f3 * al4.w;
        float pb = f0 * ar4.x + f1 * ar4.y + f2 * ar4.z + f3 * ar4.w;
#pragma unroll
        for (int off = 4; off > 0; off >>= 1) {
            pa += __shfl_down_sync(0xFFFFFFFFu, pa, off, 8);
            pb += __shfl_down_sync(0xFFFFFFFFu, pb, off, 8);
        }
        if (node < N) {
            *(float4*)(feat + node * 128 + col0) = make_float4(f0, f1, f2, f3);
            if ((c & 7) == 0) {
                el[node * 4 + head] = pa;
                er[node * 4 + head] = pb;
            }
        }
    }
}

// ---------------- layer2 fc (K=128 -> OUT=4, H=1), one warp per node ---------
__global__ void gemm2_kernel(const float* __restrict__ h,
                             const float* __restrict__ W,
                             const float* __restrict__ al,
                             const float* __restrict__ ar,
                             float* __restrict__ feat2,
                             float* __restrict__ el,
                             float* __restrict__ er,
                             int N) {
    int warp = (blockIdx.x * blockDim.x + threadIdx.x) >> 5;
    int lane = threadIdx.x & 31;
    if (warp >= N) return;

    float a0 = 0.f, a1 = 0.f, a2 = 0.f, a3 = 0.f;
#pragma unroll
    for (int i = 0; i < 4; i++) {
        int k = lane + 32 * i;
        float hv = h[warp * 128 + k];
        const float4 w = *(const float4*)(W + k * 4);
        a0 += hv * w.x; a1 += hv * w.y; a2 += hv * w.z; a3 += hv * w.w;
    }
#pragma unroll
    for (int o = 16; o > 0; o >>= 1) {
        a0 += __shfl_xor_sync(0xFFFFFFFFu, a0, o);
        a1 += __shfl_xor_sync(0xFFFFFFFFu, a1, o);
        a2 += __shfl_xor_sync(0xFFFFFFFFu, a2, o);
        a3 += __shfl_xor_sync(0xFFFFFFFFu, a3, o);
    }
    if (lane == 0) {
        feat2[warp * 4 + 0] = a0;
        feat2[warp * 4 + 1] = a1;
        feat2[warp * 4 + 2] = a2;
        feat2[warp * 4 + 3] = a3;
        el[warp] = a0 * al[0] + a1 * al[1] + a2 * al[2] + a3 * al[3];
        er[warp] = a0 * ar[0] + a1 * ar[1] + a2 * ar[2] + a3 * ar[3];
    }
}

// ---------------- fused aggregation (layers 0,1): one warp per dst ------------
// lane l covers feat cols 4l..4l+3 (head = l>>3). exp computed in lanes 0-3,
// shuffled. Register accumulation, fused normalize+bias+resid+ELU epilogue.
__global__ void aggr_warp_kernel(const int* __restrict__ rowptr,
                                 const int* __restrict__ csrsrc,
                                 const float* __restrict__ el,
                                 const float* __restrict__ er,
                                 const float* __restrict__ feat,
                                 const float* __restrict__ bias,
                                 const float* __restrict__ resid,
                                 float* __restrict__ rst,
                                 int N, int applyAct) {
    int di = (blockIdx.x * blockDim.x + threadIdx.x) >> 5;
    int lane = threadIdx.x & 31;
    if (di >= N) return;

    int row0 = rowptr[di];
    int deg = rowptr[di + 1] - row0;
    int head = lane >> 3;
    float er_l = (lane < 4) ? er[di * 4 + lane] : 0.0f;

    float4 acc = make_float4(0.f, 0.f, 0.f, 0.f);
    float sexp = 0.0f;

    int e = 0;
    for (; e + 2 <= deg; e += 2) {
        int si0 = csrsrc[row0 + e];
        int si1 = csrsrc[row0 + e + 1];
        float ex4a = 0.f, ex4b = 0.f;
        if (lane < 4) {
            float v0 = el[si0 * 4 + lane] + er_l;
            float v1 = el[si1 * 4 + lane] + er_l;
            v0 = (v0 > 0.f) ? v0 : NEG_SLOPE * v0;
            v1 = (v1 > 0.f) ? v1 : NEG_SLOPE * v1;
            ex4a = __expf(v0);
            ex4b = __expf(v1);
        }
        float exa = __shfl_sync(0xFFFFFFFFu, ex4a, head);
        float exb = __shfl_sync(0xFFFFFFFFu, ex4b, head);
        const float4 fa = *(const float4*)(feat + si0 * 128 + lane * 4);
        const float4 fb = *(const float4*)(feat + si1 * 128 + lane * 4);
        acc.x += exa * fa.x + exb * fb.x;
        acc.y += exa * fa.y + exb * fb.y;
        acc.z += exa * fa.z + exb * fb.z;
        acc.w += exa * fa.w + exb * fb.w;
        sexp += exa + exb;
    }
    if (e < deg) {
        int si = csrsrc[row0 + e];
        float ex4 = 0.f;
        if (lane < 4) {
            float v = el[si * 4 + lane] + er_l;
            v = (v > 0.f) ? v : NEG_SLOPE * v;
            ex4 = __expf(v);
        }
        float ex = __shfl_sync(0xFFFFFFFFu, ex4, head);
        const float4 f = *(const float4*)(feat + si * 128 + lane * 4);
        acc.x += ex * f.x; acc.y += ex * f.y;
        acc.z += ex * f.z; acc.w += ex * f.w;
        sexp += ex;
    }

    float inv = (sexp > 0.0f) ? 1.0f / sexp : 0.0f;
    int idx = di * 128 + lane * 4;
    const float4 b4 = *(const float4*)(bias + lane * 4);
    float4 v = make_float4(acc.x * inv + b4.x, acc.y * inv + b4.y,
                           acc.z * inv + b4.z, acc.w * inv + b4.w);
    if (resid) {
        const float4 r4 = *(const float4*)(resid + idx);
        v.x += r4.x; v.y += r4.y; v.z += r4.z; v.w += r4.w;
    }
    if (applyAct) {
        v.x = (v.x > 0.f) ? v.x : (__expf(v.x) - 1.0f);
        v.y = (v.y > 0.f) ? v.y : (__expf(v.y) - 1.0f);
        v.z = (v.z > 0.f) ? v.z : (__expf(v.z) - 1.0f);
        v.w = (v.w > 0.f) ? v.w : (__expf(v.w) - 1.0f);
    }
    *(float4*)(rst + idx) = v;
}

// ---------------- fused aggregation (layer 2, H=1, D=4) ----------------------
__global__ void aggr2_kernel(const int* __restrict__ rowptr,
                             const int* __restrict__ csrsrc,
                             const float* __restrict__ el,
                             const float* __restrict__ er,
                             const float* __restrict__ feat2,
                             const float* __restrict__ bias,
                             float* __restrict__ out,
                             int N) {
    int di = (blockIdx.x * blockDim.x + threadIdx.x) >> 5;
    int lane = threadIdx.x & 31;
    if (di >= N) return;

    int row0 = rowptr[di];
    int deg = rowptr[di + 1] - row0;
    float erd = er[di];

    float a0 = 0.f, a1 = 0.f, a2 = 0.f, a3 = 0.f, sexp = 0.f;
    for (int e = lane; e < deg; e += 32) {
        int si = csrsrc[row0 + e];
        float v = el[si] + erd;
        v = (v > 0.f) ? v : NEG_SLOPE * v;
        float ex = __expf(v);
        const float4 f = *(const float4*)(feat2 + si * 4);
        a0 += ex * f.x; a1 += ex * f.y; a2 += ex * f.z; a3 += ex * f.w;
        sexp += ex;
    }
#pragma unroll
    for (int o = 16; o > 0; o >>= 1) {
        a0 += __shfl_xor_sync(0xFFFFFFFFu, a0, o);
        a1 += __shfl_xor_sync(0xFFFFFFFFu, a1, o);
        a2 += __shfl_xor_sync(0xFFFFFFFFu, a2, o);
        a3 += __shfl_xor_sync(0xFFFFFFFFu, a3, o);
        sexp += __shfl_xor_sync(0xFFFFFFFFu, sexp, o);
    }
    if (lane == 0) {
        float inv = (sexp > 0.0f) ? 1.0f / sexp : 0.0f;
        out[di * 4 + 0] = a0 * inv + bias[0];
        out[di * 4 + 1] = a1 * inv + bias[1];
        out[di * 4 + 2] = a2 * inv + bias[2];
        out[di * 4 + 3] = a3 * inv + bias[3];
    }
}

// ---------------- host launcher ----------------------------------------------
extern "C" void kernel_launch(void* const* d_in, const int* in_sizes, int n_in,
                              void* d_out, int out_size) {
    const float* x   = (const float*)d_in[0];
    const int*   src = (const int*)d_in[1];
    const int*   dst = (const int*)d_in[2];
    const float* W0  = (const float*)d_in[3];
    const float* al0 = (const float*)d_in[4];
    const float* ar0 = (const float*)d_in[5];
    const float* b0  = (const float*)d_in[6];
    const float* W1  = (const float*)d_in[7];
    const float* al1 = (const float*)d_in[8];
    const float* ar1 = (const float*)d_in[9];
    const float* b1  = (const float*)d_in[10];
    const float* W2  = (const float*)d_in[11];
    const float* al2 = (const float*)d_in[12];
    const float* ar2 = (const float*)d_in[13];
    const float* b2  = (const float*)d_in[14];

    int N = in_sizes[0] / 64;
    int E = in_sizes[1];

    float *feat, *rstA, *rstB, *el, *er, *feat2;
    int *count, *rowptr, *cursor, *csrsrc;
    cudaGetSymbolAddress((void**)&feat,   g_feat);
    cudaGetSymbolAddress((void**)&rstA,   g_rstA);
    cudaGetSymbolAddress((void**)&rstB,   g_rstB);
    cudaGetSymbolAddress((void**)&el,     g_el);
    cudaGetSymbolAddress((void**)&er,     g_er);
    cudaGetSymbolAddress((void**)&feat2,  g_feat2);
    cudaGetSymbolAddress((void**)&count,  g_count);
    cudaGetSymbolAddress((void**)&rowptr, g_rowptr);
    cudaGetSymbolAddress((void**)&cursor, g_cursor);
    cudaGetSymbolAddress((void**)&csrsrc, g_csrsrc);

    float* out = (float*)d_out;

    const int TB = 256;
    int gridE = (E + TB - 1) / TB;
    int gridGemm = (N + 31) / 32;
    int gridWarpN = (N * 32 + TB - 1) / TB;   // warp per node

    // ---------- CSR build ----------
    cudaMemsetAsync(count, 0, N * sizeof(int));
    count_kernel<<<gridE, TB>>>(dst, count, E);
    scan_kernel<<<1, 1024>>>(count, rowptr, cursor, N);
    fill_csr_kernel<<<gridE, TB>>>(src, dst, cursor, csrsrc, E);

    // ---------- layer 0 (K=64) ----------
    gemm_attn2_kernel<<<gridGemm, 256>>>(x, W0, al0, ar0, feat, el, er, 64, N);
    aggr_warp_kernel<<<gridWarpN, TB>>>(rowptr, csrsrc, el, er, feat, b0, nullptr, rstA, N, 1);

    // ---------- layer 1 (K=128, residual) ----------
    gemm_attn2_kernel<<<gridGemm, 256>>>(rstA, W1, al1, ar1, feat, el, er, 128, N);
    aggr_warp_kernel<<<gridWarpN, TB>>>(rowptr, csrsrc, el, er, feat, b1, rstA, rstB, N, 1);

    // ---------- layer 2 (K=128 -> 4, H=1) ----------
    gemm2_kernel<<<gridWarpN, TB>>>(rstB, W2, al2, ar2, feat2, el, er, N);
    aggr2_kernel<<<gridWarpN, TB>>>(rowptr, csrsrc, el, er, feat2, b2, out, N);
}

// round 8
// speedup vs baseline: 1.9052x; 1.0443x over previous
#include <cuda_runtime.h>
#include <cuda_bf16.h>
#include <math.h>

#define NMAX 50000
#define EMAX 800000
#define NEG_SLOPE 0.2f

// ---------------- static device scratch --------------------------------------
__device__ float g_feat[NMAX * 128];   // current layer fc output [N,H*D]
__device__ float g_rstA[NMAX * 128];   // layer0 output (h1)
__device__ float g_rstB[NMAX * 128];   // layer1 output (h2)
__device__ float g_el[NMAX * 4];
__device__ float g_er[NMAX * 4];
__device__ float g_feat2[NMAX * 4];    // layer2 fc output
__device__ int   g_count[NMAX];
__device__ int   g_rowptr[NMAX + 1];
__device__ int   g_cursor[NMAX];
__device__ int   g_csrsrc[EMAX];

// ---------------- f32x2 packed helpers (Blackwell) ---------------------------
__device__ __forceinline__ unsigned long long pack2(float x) {
    unsigned long long r;
    asm("mov.b64 %0, {%1, %1};" : "=l"(r) : "f"(x));
    return r;
}
__device__ __forceinline__ unsigned long long packpair(float lo, float hi) {
    unsigned long long r;
    asm("mov.b64 %0, {%1, %2};" : "=l"(r) : "f"(lo), "f"(hi));
    return r;
}
__device__ __forceinline__ unsigned long long fma2(unsigned long long a,
                                                   unsigned long long b,
                                                   unsigned long long c) {
    unsigned long long d;
    asm("fma.rn.f32x2 %0, %1, %2, %3;" : "=l"(d) : "l"(a), "l"(b), "l"(c));
    return d;
}
__device__ __forceinline__ void unpack2(unsigned long long p, float& lo, float& hi) {
    asm("mov.b64 {%0, %1}, %2;" : "=f"(lo), "=f"(hi) : "l"(p));
}

// ---------------- CSR build ---------------------------------------------------
__global__ void count_kernel(const int* __restrict__ dst, int* __restrict__ count,
                             int E) {
    int e = blockIdx.x * blockDim.x + threadIdx.x;
    if (e < E) atomicAdd(&count[dst[e]], 1);
}

__global__ void scan_kernel(const int* __restrict__ count,
                            int* __restrict__ rowptr,
                            int* __restrict__ cursor, int n) {
    __shared__ int ssum[1024];
    int t = threadIdx.x;
    int chunk = (n + 1023) >> 10;
    int begin = t * chunk;
    int end = min(begin + chunk, n);
    int sum = 0;
    for (int i = begin; i < end; i++) sum += count[i];
    ssum[t] = sum;
    __syncthreads();
    for (int off = 1; off < 1024; off <<= 1) {
        int v = (t >= off) ? ssum[t - off] : 0;
        __syncthreads();
        ssum[t] += v;
        __syncthreads();
    }
    int prefix = (t == 0) ? 0 : ssum[t - 1];
    for (int i = begin; i < end; i++) {
        rowptr[i] = prefix;
        cursor[i] = prefix;
        prefix += count[i];
    }
    if (t == 0) rowptr[n] = ssum[1023];
}

__global__ void fill_csr_kernel(const int* __restrict__ src,
                                const int* __restrict__ dst,
                                int* __restrict__ cursor,
                                int* __restrict__ csrsrc, int E) {
    int e = blockIdx.x * blockDim.x + threadIdx.x;
    if (e < E) {
        int pos = atomicAdd(&cursor[dst[e]], 1);
        csrsrc[pos] = src[e];
    }
}

// ---------------- register-tiled fc + attention projections ------------------
// Block = 256 threads, tile = 32 nodes x 128 cols. Thread (c = t&31, r = t>>5)
// computes 4 nodes (r*4..r*4+3) x 4 cols (c*4..c*4+3) with f32x2 FMAs.
// K templated so the k-loop unrolls and LDGs batch (MLP).
#define HST_STRIDE 36
template <int K>
__global__ void gemm_attn2_kernel(const float* __restrict__ h,
                                  const float* __restrict__ W,
                                  const float* __restrict__ al,
                                  const float* __restrict__ ar,
                                  float* __restrict__ feat,
                                  float* __restrict__ el,
                                  float* __restrict__ er,
                                  int N) {
    __shared__ float hsT[128 * HST_STRIDE];   // [k][node], padded
    int t = threadIdx.x;
    int node0 = blockIdx.x * 32;

    // cooperative transpose-load of h tile: 32 nodes x K floats
#pragma unroll 4
    for (int idx = t; idx < 32 * K; idx += 256) {
        int node = idx / K;
        int k = idx - node * K;
        float v = (node0 + node < N) ? h[(node0 + node) * K + k] : 0.0f;
        hsT[k * HST_STRIDE + node] = v;
    }
    __syncthreads();

    int c = t & 31;
    int r = t >> 5;
    int col0 = c * 4;

    unsigned long long acc00 = 0, acc01 = 0, acc10 = 0, acc11 = 0;
    unsigned long long acc20 = 0, acc21 = 0, acc30 = 0, acc31 = 0;

#pragma unroll 8
    for (int k = 0; k < K; k++) {
        const float4 w = *(const float4*)(W + k * 128 + col0);
        unsigned long long w01 = packpair(w.x, w.y);
        unsigned long long w23 = packpair(w.z, w.w);
        const float4 hv = *(const float4*)(&hsT[k * HST_STRIDE + r * 4]);
        unsigned long long h0 = pack2(hv.x);
        unsigned long long h1 = pack2(hv.y);
        unsigned long long h2 = pack2(hv.z);
        unsigned long long h3 = pack2(hv.w);
        acc00 = fma2(h0, w01, acc00);  acc01 = fma2(h0, w23, acc01);
        acc10 = fma2(h1, w01, acc10);  acc11 = fma2(h1, w23, acc11);
        acc20 = fma2(h2, w01, acc20);  acc21 = fma2(h2, w23, acc21);
        acc30 = fma2(h3, w01, acc30);  acc31 = fma2(h3, w23, acc31);
    }

    int head = c >> 3;
    const float4 al4 = *(const float4*)(al + col0);
    const float4 ar4 = *(const float4*)(ar + col0);

    unsigned long long accs[4][2] = {{acc00, acc01}, {acc10, acc11},
                                     {acc20, acc21}, {acc30, acc31}};
#pragma unroll
    for (int n = 0; n < 4; n++) {
        int node = node0 + r * 4 + n;
        float f0, f1, f2, f3;
        unpack2(accs[n][0], f0, f1);
        unpack2(accs[n][1], f2, f3);
        float pa = f0 * al4.x + f1 * al4.y + f2 * al4.z + f3 * al4.w;
        float pb = f0 * ar4.x + f1 * ar4.y + f2 * ar4.z + f3 * ar4.w;
#pragma unroll
        for (int off = 4; off > 0; off >>= 1) {
            pa += __shfl_down_sync(0xFFFFFFFFu, pa, off, 8);
            pb += __shfl_down_sync(0xFFFFFFFFu, pb, off, 8);
        }
        if (node < N) {
            *(float4*)(feat + node * 128 + col0) = make_float4(f0, f1, f2, f3);
            if ((c & 7) == 0) {
                el[node * 4 + head] = pa;
                er[node * 4 + head] = pb;
            }
        }
    }
}

// ---------------- layer2 fc (K=128 -> OUT=4, H=1), one warp per node ---------
__global__ void gemm2_kernel(const float* __restrict__ h,
                             const float* __restrict__ W,
                             const float* __restrict__ al,
                             const float* __restrict__ ar,
                             float* __restrict__ feat2,
                             float* __restrict__ el,
                             float* __restrict__ er,
                             int N) {
    int warp = (blockIdx.x * blockDim.x + threadIdx.x) >> 5;
    int lane = threadIdx.x & 31;
    if (warp >= N) return;

    float a0 = 0.f, a1 = 0.f, a2 = 0.f, a3 = 0.f;
#pragma unroll
    for (int i = 0; i < 4; i++) {
        int k = lane + 32 * i;
        float hv = h[warp * 128 + k];
        const float4 w = *(const float4*)(W + k * 4);
        a0 += hv * w.x; a1 += hv * w.y; a2 += hv * w.z; a3 += hv * w.w;
    }
#pragma unroll
    for (int o = 16; o > 0; o >>= 1) {
        a0 += __shfl_xor_sync(0xFFFFFFFFu, a0, o);
        a1 += __shfl_xor_sync(0xFFFFFFFFu, a1, o);
        a2 += __shfl_xor_sync(0xFFFFFFFFu, a2, o);
        a3 += __shfl_xor_sync(0xFFFFFFFFu, a3, o);
    }
    if (lane == 0) {
        feat2[warp * 4 + 0] = a0;
        feat2[warp * 4 + 1] = a1;
        feat2[warp * 4 + 2] = a2;
        feat2[warp * 4 + 3] = a3;
        el[warp] = a0 * al[0] + a1 * al[1] + a2 * al[2] + a3 * al[3];
        er[warp] = a0 * ar[0] + a1 * ar[1] + a2 * ar[2] + a3 * ar[3];
    }
}

// ---------------- fused aggregation (layers 0,1): one warp per dst ------------
// 4-way edge unroll for MLP. lane l covers feat cols 4l..4l+3 (head = l>>3).
__global__ void aggr_warp_kernel(const int* __restrict__ rowptr,
                                 const int* __restrict__ csrsrc,
                                 const float* __restrict__ el,
                                 const float* __restrict__ er,
                                 const float* __restrict__ feat,
                                 const float* __restrict__ bias,
                                 const float* __restrict__ resid,
                                 float* __restrict__ rst,
                                 int N, int applyAct) {
    int di = (blockIdx.x * blockDim.x + threadIdx.x) >> 5;
    int lane = threadIdx.x & 31;
    if (di >= N) return;

    int row0 = rowptr[di];
    int deg = rowptr[di + 1] - row0;
    int head = lane >> 3;
    float er_l = (lane < 4) ? er[di * 4 + lane] : 0.0f;

    float4 acc = make_float4(0.f, 0.f, 0.f, 0.f);
    float sexp = 0.0f;

    int e = 0;
    for (; e + 4 <= deg; e += 4) {
        int si0 = csrsrc[row0 + e];
        int si1 = csrsrc[row0 + e + 1];
        int si2 = csrsrc[row0 + e + 2];
        int si3 = csrsrc[row0 + e + 3];
        float x0 = 0.f, x1 = 0.f, x2 = 0.f, x3 = 0.f;
        if (lane < 4) {
            float v0 = el[si0 * 4 + lane] + er_l;
            float v1 = el[si1 * 4 + lane] + er_l;
            float v2 = el[si2 * 4 + lane] + er_l;
            float v3 = el[si3 * 4 + lane] + er_l;
            v0 = (v0 > 0.f) ? v0 : NEG_SLOPE * v0;
            v1 = (v1 > 0.f) ? v1 : NEG_SLOPE * v1;
            v2 = (v2 > 0.f) ? v2 : NEG_SLOPE * v2;
            v3 = (v3 > 0.f) ? v3 : NEG_SLOPE * v3;
            x0 = __expf(v0); x1 = __expf(v1);
            x2 = __expf(v2); x3 = __expf(v3);
        }
        float exa = __shfl_sync(0xFFFFFFFFu, x0, head);
        float exb = __shfl_sync(0xFFFFFFFFu, x1, head);
        float exc = __shfl_sync(0xFFFFFFFFu, x2, head);
        float exd = __shfl_sync(0xFFFFFFFFu, x3, head);
        const float4 fa = *(const float4*)(feat + si0 * 128 + lane * 4);
        const float4 fb = *(const float4*)(feat + si1 * 128 + lane * 4);
        const float4 fc = *(const float4*)(feat + si2 * 128 + lane * 4);
        const float4 fd = *(const float4*)(feat + si3 * 128 + lane * 4);
        acc.x += exa * fa.x + exb * fb.x + exc * fc.x + exd * fd.x;
        acc.y += exa * fa.y + exb * fb.y + exc * fc.y + exd * fd.y;
        acc.z += exa * fa.z + exb * fb.z + exc * fc.z + exd * fd.z;
        acc.w += exa * fa.w + exb * fb.w + exc * fc.w + exd * fd.w;
        sexp += exa + exb + exc + exd;
    }
    for (; e < deg; e++) {
        int si = csrsrc[row0 + e];
        float ex4 = 0.f;
        if (lane < 4) {
            float v = el[si * 4 + lane] + er_l;
            v = (v > 0.f) ? v : NEG_SLOPE * v;
            ex4 = __expf(v);
        }
        float ex = __shfl_sync(0xFFFFFFFFu, ex4, head);
        const float4 f = *(const float4*)(feat + si * 128 + lane * 4);
        acc.x += ex * f.x; acc.y += ex * f.y;
        acc.z += ex * f.z; acc.w += ex * f.w;
        sexp += ex;
    }

    float inv = (sexp > 0.0f) ? 1.0f / sexp : 0.0f;
    int idx = di * 128 + lane * 4;
    const float4 b4 = *(const float4*)(bias + lane * 4);
    float4 v = make_float4(acc.x * inv + b4.x, acc.y * inv + b4.y,
                           acc.z * inv + b4.z, acc.w * inv + b4.w);
    if (resid) {
        const float4 r4 = *(const float4*)(resid + idx);
        v.x += r4.x; v.y += r4.y; v.z += r4.z; v.w += r4.w;
    }
    if (applyAct) {
        v.x = (v.x > 0.f) ? v.x : (__expf(v.x) - 1.0f);
        v.y = (v.y > 0.f) ? v.y : (__expf(v.y) - 1.0f);
        v.z = (v.z > 0.f) ? v.z : (__expf(v.z) - 1.0f);
        v.w = (v.w > 0.f) ? v.w : (__expf(v.w) - 1.0f);
    }
    *(float4*)(rst + idx) = v;
}

// ---------------- fused aggregation (layer 2, H=1, D=4) ----------------------
__global__ void aggr2_kernel(const int* __restrict__ rowptr,
                             const int* __restrict__ csrsrc,
                             const float* __restrict__ el,
                             const float* __restrict__ er,
                             const float* __restrict__ feat2,
                             const float* __restrict__ bias,
                             float* __restrict__ out,
                             int N) {
    int di = (blockIdx.x * blockDim.x + threadIdx.x) >> 5;
    int lane = threadIdx.x & 31;
    if (di >= N) return;

    int row0 = rowptr[di];
    int deg = rowptr[di + 1] - row0;
    float erd = er[di];

    float a0 = 0.f, a1 = 0.f, a2 = 0.f, a3 = 0.f, sexp = 0.f;
    for (int e = lane; e < deg; e += 32) {
        int si = csrsrc[row0 + e];
        float v = el[si] + erd;
        v = (v > 0.f) ? v : NEG_SLOPE * v;
        float ex = __expf(v);
        const float4 f = *(const float4*)(feat2 + si * 4);
        a0 += ex * f.x; a1 += ex * f.y; a2 += ex * f.z; a3 += ex * f.w;
        sexp += ex;
    }
#pragma unroll
    for (int o = 16; o > 0; o >>= 1) {
        a0 += __shfl_xor_sync(0xFFFFFFFFu, a0, o);
        a1 += __shfl_xor_sync(0xFFFFFFFFu, a1, o);
        a2 += __shfl_xor_sync(0xFFFFFFFFu, a2, o);
        a3 += __shfl_xor_sync(0xFFFFFFFFu, a3, o);
        sexp += __shfl_xor_sync(0xFFFFFFFFu, sexp, o);
    }
    if (lane == 0) {
        float inv = (sexp > 0.0f) ? 1.0f / sexp : 0.0f;
        out[di * 4 + 0] = a0 * inv + bias[0];
        out[di * 4 + 1] = a1 * inv + bias[1];
        out[di * 4 + 2] = a2 * inv + bias[2];
        out[di * 4 + 3] = a3 * inv + bias[3];
    }
}

// ---------------- host launcher ----------------------------------------------
extern "C" void kernel_launch(void* const* d_in, const int* in_sizes, int n_in,
                              void* d_out, int out_size) {
    const float* x   = (const float*)d_in[0];
    const int*   src = (const int*)d_in[1];
    const int*   dst = (const int*)d_in[2];
    const float* W0  = (const float*)d_in[3];
    const float* al0 = (const float*)d_in[4];
    const float* ar0 = (const float*)d_in[5];
    const float* b0  = (const float*)d_in[6];
    const float* W1  = (const float*)d_in[7];
    const float* al1 = (const float*)d_in[8];
    const float* ar1 = (const float*)d_in[9];
    const float* b1  = (const float*)d_in[10];
    const float* W2  = (const float*)d_in[11];
    const float* al2 = (const float*)d_in[12];
    const float* ar2 = (const float*)d_in[13];
    const float* b2  = (const float*)d_in[14];

    int N = in_sizes[0] / 64;
    int E = in_sizes[1];

    float *feat, *rstA, *rstB, *el, *er, *feat2;
    int *count, *rowptr, *cursor, *csrsrc;
    cudaGetSymbolAddress((void**)&feat,   g_feat);
    cudaGetSymbolAddress((void**)&rstA,   g_rstA);
    cudaGetSymbolAddress((void**)&rstB,   g_rstB);
    cudaGetSymbolAddress((void**)&el,     g_el);
    cudaGetSymbolAddress((void**)&er,     g_er);
    cudaGetSymbolAddress((void**)&feat2,  g_feat2);
    cudaGetSymbolAddress((void**)&count,  g_count);
    cudaGetSymbolAddress((void**)&rowptr, g_rowptr);
    cudaGetSymbolAddress((void**)&cursor, g_cursor);
    cudaGetSymbolAddress((void**)&csrsrc, g_csrsrc);

    float* out = (float*)d_out;

    const int TB = 256;
    int gridE = (E + TB - 1) / TB;
    int gridGemm = (N + 31) / 32;
    int gridWarpN = (N * 32 + TB - 1) / TB;   // warp per node

    // ---------- CSR build ----------
    cudaMemsetAsync(count, 0, N * sizeof(int));
    count_kernel<<<gridE, TB>>>(dst, count, E);
    scan_kernel<<<1, 1024>>>(count, rowptr, cursor, N);
    fill_csr_kernel<<<gridE, TB>>>(src, dst, cursor, csrsrc, E);

    // ---------- layer 0 (K=64) ----------
    gemm_attn2_kernel<64><<<gridGemm, 256>>>(x, W0, al0, ar0, feat, el, er, N);
    aggr_warp_kernel<<<gridWarpN, TB>>>(rowptr, csrsrc, el, er, feat, b0, nullptr, rstA, N, 1);

    // ---------- layer 1 (K=128, residual) ----------
    gemm_attn2_kernel<128><<<gridGemm, 256>>>(rstA, W1, al1, ar1, feat, el, er, N);
    aggr_warp_kernel<<<gridWarpN, TB>>>(rowptr, csrsrc, el, er, feat, b1, rstA, rstB, N, 1);

    // ---------- layer 2 (K=128 -> 4, H=1) ----------
    gemm2_kernel<<<gridWarpN, TB>>>(rstB, W2, al2, ar2, feat2, el, er, N);
    aggr2_kernel<<<gridWarpN, TB>>>(rowptr, csrsrc, el, er, feat2, b2, out, N);
}